// round 13
// baseline (speedup 1.0000x reference)
#include <cuda_runtime.h>

// Problem constants: B=8, T=4096, C=32 (embedding), D=64 (head)
#define B_  8
#define T_  4096
#define C_  32
#define D_  64
#define NQT128 32            // 128-wide query tiles per batch
#define NCHUNK 8             // k-chunks per query tile (each <=8 k-passes of 64)

typedef unsigned long long ull;

// ---- attn kernel smem layout (floats), double-buffered x tiles ----
#define QP2    132                     // ys row stride (128 q + pad)
#define YS_OFF 0                       // ys[32][132]   = 4224
#define XT_STR (32 * 68)               // one xT buffer = 2176
#define XT_OFF 4224                    // xT[2][32][68] = 4352
#define XN_STR (64 * 36)               // one xN buffer = 2304
#define XN_OFF (XT_OFF + 2 * XT_STR)   // xN[2][64][36] = 4608
#define PS_OFF (XN_OFF + 2 * XN_STR)   // Ps[128][68]   = 8704
#define SM_FLOATS (PS_OFF + 128 * 68)  // 21888 floats = 87552 B -> 2 CTAs/SM

// y = x * (Wq Wk^T)  [B*T, 32]
__device__ float g_y[B_ * T_ * C_];
// split-K partials: slot = ((b*32+qt)*8 + chunk)
__device__ float g_partZ[B_ * NQT128 * NCHUNK * 128 * 32];   // 33.5 MB
__device__ float g_partL[B_ * NQT128 * NCHUNK * 128];

// ---------------------------------------------------------------------------
// packed f32x2 helpers (sm_103a FFMA2 path)
// ---------------------------------------------------------------------------
__device__ __forceinline__ ull pack2(float a, float b) {
    ull r; asm("mov.b64 %0, {%1, %2};" : "=l"(r) : "f"(a), "f"(b)); return r;
}
__device__ __forceinline__ float2 unpack2(ull v) {
    float2 r; asm("mov.b64 {%0, %1}, %2;" : "=f"(r.x), "=f"(r.y) : "l"(v)); return r;
}
__device__ __forceinline__ void fma2(ull& d, ull a, ull b) {
    asm("fma.rn.f32x2 %0, %1, %2, %0;" : "+l"(d) : "l"(a), "l"(b));
}

// ---------------------------------------------------------------------------
// Kernel 0: y = x * (Wq Wk^T).  One CTA = 128 rows.  M computed per-CTA from
// conflict-free transposed-staged weights (cheap at 256 parallel CTAs; this
// removes the serialized m_kernel entirely).
// ---------------------------------------------------------------------------
__global__ __launch_bounds__(256) void y_kernel(
    const float* __restrict__ x, const float* __restrict__ Wk,
    const float* __restrict__ Wq)
{
    __shared__ float Wqt[64 * 33];
    __shared__ float Wkt[64 * 33];
    __shared__ float Ms[32 * 34];
    __shared__ float xs[128 * 36];
    __shared__ float ysb[128 * 36];

    const int tid  = threadIdx.x;
    const int row0 = blockIdx.x * 128;

    // stage weights transposed (stride 33) + x tile
    {
        const float4* wq = (const float4*)Wq;
        const float4* wk = (const float4*)Wk;
        #pragma unroll
        for (int it = 0; it < 2; it++) {
            int lin = tid + it * 256;            // 0..511: 32 rows x 16 float4
            int r = lin >> 4, d0 = (lin & 15) * 4;
            float4 q4 = wq[lin];
            Wqt[(d0 + 0) * 33 + r] = q4.x;
            Wqt[(d0 + 1) * 33 + r] = q4.y;
            Wqt[(d0 + 2) * 33 + r] = q4.z;
            Wqt[(d0 + 3) * 33 + r] = q4.w;
            float4 k4 = wk[lin];
            Wkt[(d0 + 0) * 33 + r] = k4.x;
            Wkt[(d0 + 1) * 33 + r] = k4.y;
            Wkt[(d0 + 2) * 33 + r] = k4.z;
            Wkt[(d0 + 3) * 33 + r] = k4.w;
        }
        const float4* xg = (const float4*)(x + row0 * C_);
        #pragma unroll
        for (int it = 0; it < 4; it++) {
            int lin = tid + it * 256;            // 0..1023
            int r = lin >> 3, c4 = lin & 7;
            *(float4*)&xs[r * 36 + c4 * 4] = xg[lin];
        }
    }
    __syncthreads();

    // M[i][j] = dot(Wq row i, Wk row j) — conflict-free
    {
        const int i  = tid >> 3;
        const int j0 = (tid & 7) * 4;
        float a0 = 0.f, a1 = 0.f, a2 = 0.f, a3 = 0.f;
        #pragma unroll 16
        for (int d = 0; d < D_; d++) {
            float qv = Wqt[d * 33 + i];
            const float* wkr = &Wkt[d * 33 + j0];
            a0 += qv * wkr[0];
            a1 += qv * wkr[1];
            a2 += qv * wkr[2];
            a3 += qv * wkr[3];
        }
        Ms[i * 34 + j0 + 0] = a0;
        Ms[i * 34 + j0 + 1] = a1;
        Ms[i * 34 + j0 + 2] = a2;
        Ms[i * 34 + j0 + 3] = a3;
    }
    __syncthreads();

    // y-tile = xs * M
    {
        const int tx = tid & 15, ty = tid >> 4;
        const int c0 = tx * 2;
        float a0[8], a1[8];
        #pragma unroll
        for (int i = 0; i < 8; i++) { a0[i] = 0.f; a1[i] = 0.f; }
        #pragma unroll 8
        for (int c = 0; c < C_; c++) {
            float2 m2 = *(const float2*)&Ms[c * 34 + c0];
            #pragma unroll
            for (int i = 0; i < 8; i++) {
                float xv = xs[(ty * 8 + i) * 36 + c];
                a0[i] += xv * m2.x;
                a1[i] += xv * m2.y;
            }
        }
        #pragma unroll
        for (int i = 0; i < 8; i++) {
            ysb[(ty * 8 + i) * 36 + c0 + 0] = a0[i];
            ysb[(ty * 8 + i) * 36 + c0 + 1] = a1[i];
        }
    }
    __syncthreads();

    // coalesced store
    {
        float4* yg = (float4*)(g_y + row0 * C_);
        #pragma unroll
        for (int it = 0; it < 4; it++) {
            int lin = tid + it * 256;
            int r = lin >> 3, c4 = lin & 7;
            yg[lin] = *(const float4*)&ysb[r * 36 + c4 * 4];
        }
    }
}

// ---------------------------------------------------------------------------
// Kernel 1: split-K attention partials (R11 structure: 2 CTAs/SM,
// double-buffered x tiles, 2 syncs/pass).
// One CTA = (b, qt, chunk): k-tiles [8*chunk, min(2qt+2, 8*chunk+8)).
//   S = y x_k^T (inner 32);  p = exp(S);  Zpart += p x_k;  lpart += rowsum(p)
// Z-pass: 2 rows (rs, rs+64) x 8 cols per thread — halves the pd dup-packs.
// ---------------------------------------------------------------------------
__global__ __launch_bounds__(256, 2) void attn_kernel(const float* __restrict__ x)
{
    const int b     = blockIdx.y;
    const int qt    = (NQT128 - 1) - (blockIdx.x >> 3);  // heaviest first
    const int chunk = blockIdx.x & 7;
    const int k0    = chunk * 8;
    const int k1e   = 2 * qt + 2;                        // one past last k-tile
    if (k0 >= k1e) return;                               // empty chunk
    const int k1    = (k1e < k0 + 8) ? k1e : (k0 + 8);

    extern __shared__ float smf[];
    float* ys  = smf + YS_OFF;
    float* xT0 = smf + XT_OFF;
    float* xN0 = smf + XN_OFF;
    float* Ps  = smf + PS_OFF;

    const int tid = threadIdx.x;
    const int tx  = tid & 15, ty = tid >> 4;   // S-pass: 8q x 4k per thread
    const int g   = tid & 3;                   // Z-pass col group
    const int zc  = g * 8;                     // Z-pass cols zc..zc+7
    const int rs  = tid >> 2;                  // Z-pass rows rs, rs+64

    const float* xb = x + b * T_ * C_;

    // ---- load y tile (128x32) transposed into ys[c][q] ----
    {
        const float4* yq = (const float4*)(g_y + (b * T_ + qt * 128) * C_);
        #pragma unroll
        for (int it = 0; it < 4; it++) {
            int lin = tid + it * 256;            // 0..1023
            int r = lin >> 3, c4 = lin & 7;
            float4 v = yq[lin];
            ys[(c4 * 4 + 0) * QP2 + r] = v.x;
            ys[(c4 * 4 + 1) * QP2 + r] = v.y;
            ys[(c4 * 4 + 2) * QP2 + r] = v.z;
            ys[(c4 * 4 + 3) * QP2 + r] = v.w;
        }
    }

    // ---- preload k-tile k0 into buffer 0 (natural + transposed) ----
    {
        const float4* xg = (const float4*)(xb + k0 * 64 * C_);
        float4 p0 = xg[tid], p1 = xg[tid + 256];
        int r = tid >> 3, c4 = tid & 7;
        *(float4*)&xN0[r * 36 + c4 * 4] = p0;
        xT0[(c4 * 4 + 0) * 68 + r] = p0.x;
        xT0[(c4 * 4 + 1) * 68 + r] = p0.y;
        xT0[(c4 * 4 + 2) * 68 + r] = p0.z;
        xT0[(c4 * 4 + 3) * 68 + r] = p0.w;
        int r2 = r + 32;
        *(float4*)&xN0[r2 * 36 + c4 * 4] = p1;
        xT0[(c4 * 4 + 0) * 68 + r2] = p1.x;
        xT0[(c4 * 4 + 1) * 68 + r2] = p1.y;
        xT0[(c4 * 4 + 2) * 68 + r2] = p1.z;
        xT0[(c4 * 4 + 3) * 68 + r2] = p1.w;
    }

    float l_i[8];
    #pragma unroll
    for (int i = 0; i < 8; i++) l_i[i] = 0.f;
    ull z2[2][4];   // [row i (rs, rs+64)][4 col-pairs of 8 cols]
    #pragma unroll
    for (int i = 0; i < 2; i++)
        #pragma unroll
        for (int j = 0; j < 4; j++) z2[i][j] = 0ull;

    for (int kt = k0; kt < k1; kt++) {
        const int buf = (kt - k0) & 1;
        const float* xTb = xT0 + buf * XT_STR;
        const float* xNb = xN0 + buf * XN_STR;

        __syncthreads();   // (A) this buf loaded; prior Z-pass done; ys ready

        // prefetch next k-tile into registers (stored after S-pass)
        float4 p0, p1;
        const bool pf = (kt + 1 < k1);
        if (pf) {
            const float4* xg = (const float4*)(xb + (kt + 1) * 64 * C_);
            p0 = xg[tid]; p1 = xg[tid + 256];
        }

        // ---- S = y * x_k^T : 8q x 4k, q-paired FFMA2, pair-free q loads ----
        ull s2[4][4];   // [k-col j][q-pair i2]
        #pragma unroll
        for (int j = 0; j < 4; j++)
            #pragma unroll
            for (int i2 = 0; i2 < 4; i2++) s2[j][i2] = 0ull;

        #pragma unroll 8
        for (int c = 0; c < C_; c++) {
            ulonglong2 qa = *(const ulonglong2*)&ys[c * QP2 + ty * 8];
            ulonglong2 qb = *(const ulonglong2*)&ys[c * QP2 + ty * 8 + 4];
            float4 kv = *(const float4*)&xTb[c * 68 + tx * 4];
            ull kd[4] = { pack2(kv.x, kv.x), pack2(kv.y, kv.y),
                          pack2(kv.z, kv.z), pack2(kv.w, kv.w) };
            #pragma unroll
            for (int j = 0; j < 4; j++) {
                fma2(s2[j][0], qa.x, kd[j]);
                fma2(s2[j][1], qa.y, kd[j]);
                fma2(s2[j][2], qb.x, kd[j]);
                fma2(s2[j][3], qb.y, kd[j]);
            }
        }

        float s[8][4];
        #pragma unroll
        for (int j = 0; j < 4; j++)
            #pragma unroll
            for (int i2 = 0; i2 < 4; i2++) {
                float2 u = unpack2(s2[j][i2]);
                s[2 * i2 + 0][j] = u.x;
                s[2 * i2 + 1][j] = u.y;
            }

        if (kt >= 2 * qt) {   // causal mask (last two k-tiles of this qt)
            const int koff = (kt - 2 * qt) * 64;
            #pragma unroll
            for (int i = 0; i < 8; i++)
                #pragma unroll
                for (int j = 0; j < 4; j++)
                    if (koff + tx * 4 + j > ty * 8 + i) s[i][j] = -1e30f;
        }

        // ---- store prefetched tile into other buffer ----
        if (pf) {
            const int nb = buf ^ 1;
            float* xNn = xN0 + nb * XN_STR;
            float* xTn = xT0 + nb * XT_STR;
            int r = tid >> 3, c4 = tid & 7;
            *(float4*)&xNn[r * 36 + c4 * 4] = p0;
            xTn[(c4 * 4 + 0) * 68 + r] = p0.x;
            xTn[(c4 * 4 + 1) * 68 + r] = p0.y;
            xTn[(c4 * 4 + 2) * 68 + r] = p0.z;
            xTn[(c4 * 4 + 3) * 68 + r] = p0.w;
            int r2 = r + 32;
            *(float4*)&xNn[r2 * 36 + c4 * 4] = p1;
            xTn[(c4 * 4 + 0) * 68 + r2] = p1.x;
            xTn[(c4 * 4 + 1) * 68 + r2] = p1.y;
            xTn[(c4 * 4 + 2) * 68 + r2] = p1.z;
            xTn[(c4 * 4 + 3) * 68 + r2] = p1.w;
        }

        // ---- p = exp(s), accumulate local row-sum ----
        #pragma unroll
        for (int i = 0; i < 8; i++) {
            float e0 = __expf(s[i][0]);
            float e1 = __expf(s[i][1]);
            float e2 = __expf(s[i][2]);
            float e3 = __expf(s[i][3]);
            l_i[i] += (e0 + e1) + (e2 + e3);
            *(float4*)&Ps[(ty * 8 + i) * 68 + tx * 4] = make_float4(e0, e1, e2, e3);
        }
        __syncthreads();   // (B) Ps visible

        // ---- Z += P * x_k : rows rs & rs+64, cols zc..zc+7 ----
        // x pairs pair-free from ulonglong2 loads; pd packs halved (8/k4).
        #pragma unroll 4
        for (int k4 = 0; k4 < 16; k4++) {
            ulonglong2 xA[4], xB[4];
            #pragma unroll
            for (int kk = 0; kk < 4; kk++) {
                const float* base = &xNb[(k4 * 4 + kk) * 36 + zc];
                xA[kk] = *(const ulonglong2*)base;
                xB[kk] = *(const ulonglong2*)(base + 4);
            }
            float4 pr0 = *(const float4*)&Ps[rs * 68 + k4 * 4];
            float4 pr1 = *(const float4*)&Ps[(rs + 64) * 68 + k4 * 4];

            const float* pv0 = (const float*)&pr0;
            #pragma unroll
            for (int kk = 0; kk < 4; kk++) {
                ull pd = pack2(pv0[kk], pv0[kk]);
                fma2(z2[0][0], pd, xA[kk].x);
                fma2(z2[0][1], pd, xA[kk].y);
                fma2(z2[0][2], pd, xB[kk].x);
                fma2(z2[0][3], pd, xB[kk].y);
            }
            const float* pv1 = (const float*)&pr1;
            #pragma unroll
            for (int kk = 0; kk < 4; kk++) {
                ull pd = pack2(pv1[kk], pv1[kk]);
                fma2(z2[1][0], pd, xA[kk].x);
                fma2(z2[1][1], pd, xA[kk].y);
                fma2(z2[1][2], pd, xB[kk].x);
                fma2(z2[1][3], pd, xB[kk].y);
            }
        }
    }

    // ---- write partials ----
    const int islot = (b * NQT128 + qt) * NCHUNK + chunk;

    #pragma unroll
    for (int i = 0; i < 8; i++) {   // partial row sums (reduced over tx)
        float rs_ = l_i[i];
        rs_ += __shfl_xor_sync(0xffffffffu, rs_, 8);
        rs_ += __shfl_xor_sync(0xffffffffu, rs_, 4);
        rs_ += __shfl_xor_sync(0xffffffffu, rs_, 2);
        rs_ += __shfl_xor_sync(0xffffffffu, rs_, 1);
        if (tx == 0) g_partL[islot * 128 + ty * 8 + i] = rs_;
    }

    float* zp = g_partZ + islot * (128 * 32);
    #pragma unroll
    for (int i = 0; i < 2; i++) {
        const int row = rs + 64 * i;
        float2 a0 = unpack2(z2[i][0]);
        float2 a1 = unpack2(z2[i][1]);
        float2 b0 = unpack2(z2[i][2]);
        float2 b1 = unpack2(z2[i][3]);
        *(float4*)&zp[row * 32 + zc]     = make_float4(a0.x, a0.y, a1.x, a1.y);
        *(float4*)&zp[row * 32 + zc + 4] = make_float4(b0.x, b0.y, b1.x, b1.y);
    }
}

// ---------------------------------------------------------------------------
// Kernel 2: reduce partials, out = (Z / l) * Wv.
// One CTA = (b, qt, half): 64 q-rows.  512 CTAs.
// ---------------------------------------------------------------------------
__global__ __launch_bounds__(256) void reduce_kernel(
    const float* __restrict__ Wv, float* __restrict__ out)
{
    __shared__ float Zs[64][36];
    __shared__ float Wvs[32][68];
    __shared__ float lv[64];

    const int qt   = blockIdx.x >> 1;
    const int half = blockIdx.x & 1;
    const int b    = blockIdx.y;
    const int tid  = threadIdx.x;
    const int nc   = (2 * qt + 1) / 8 + 1;   // valid chunks for this qt
    const int base = (b * NQT128 + qt) * NCHUNK;
    const int row0 = half * 64;

    float4 acc[2];
    #pragma unroll
    for (int it = 0; it < 2; it++) acc[it] = make_float4(0.f, 0.f, 0.f, 0.f);
    for (int s = 0; s < nc; s++) {
        const float4* zp = (const float4*)(g_partZ + (base + s) * (128 * 32) + row0 * 32);
        #pragma unroll
        for (int it = 0; it < 2; it++) {
            float4 v = zp[tid + it * 256];
            acc[it].x += v.x; acc[it].y += v.y; acc[it].z += v.z; acc[it].w += v.w;
        }
    }
    if (tid < 64) {
        float ls = 0.f;
        for (int s = 0; s < nc; s++)
            ls += g_partL[(base + s) * 128 + row0 + tid];
        lv[tid] = 1.f / ls;
    }
    __syncthreads();

    #pragma unroll
    for (int it = 0; it < 2; it++) {
        int lin = tid + it * 256;
        int r = lin >> 3, c4 = lin & 7;
        float li = lv[r];
        *(float4*)&Zs[r][c4 * 4] = make_float4(acc[it].x * li, acc[it].y * li,
                                               acc[it].z * li, acc[it].w * li);
    }
    {
        const float4* wg = (const float4*)Wv;
        #pragma unroll
        for (int it = 0; it < 2; it++) {
            int lin = tid + it * 256;
            int r = lin >> 4, c4 = lin & 15;
            *(float4*)&Wvs[r][c4 * 4] = wg[lin];
        }
    }
    __syncthreads();

    const int tx = tid & 15, ty = tid >> 4;
    float o[4][4];
    #pragma unroll
    for (int i = 0; i < 4; i++)
        #pragma unroll
        for (int j = 0; j < 4; j++) o[i][j] = 0.f;

    #pragma unroll 4
    for (int c = 0; c < C_; c++) {
        float4 w4 = *(const float4*)&Wvs[c][tx * 4];
        #pragma unroll
        for (int i = 0; i < 4; i++) {
            float zv = Zs[ty + 16 * i][c];
            o[i][0] += zv * w4.x; o[i][1] += zv * w4.y;
            o[i][2] += zv * w4.z; o[i][3] += zv * w4.w;
        }
    }

    float* Og = out + (b * T_ + qt * 128 + row0) * D_;
    #pragma unroll
    for (int i = 0; i < 4; i++)
        *(float4*)&Og[(ty + 16 * i) * D_ + tx * 4] =
            make_float4(o[i][0], o[i][1], o[i][2], o[i][3]);
}

// ---------------------------------------------------------------------------
extern "C" void kernel_launch(void* const* d_in, const int* in_sizes, int n_in,
                              void* d_out, int out_size)
{
    const float* x  = (const float*)d_in[0];
    const float* Wk = (const float*)d_in[1];
    const float* Wq = (const float*)d_in[2];
    const float* Wv = (const float*)d_in[3];
    float* out = (float*)d_out;

    y_kernel<<<(B_ * T_) / 128, 256>>>(x, Wk, Wq);

    const int smem = SM_FLOATS * (int)sizeof(float);   // 87552 B
    cudaFuncSetAttribute(attn_kernel, cudaFuncAttributeMaxDynamicSharedMemorySize, smem);
    attn_kernel<<<dim3(NQT128 * NCHUNK, B_), 256, smem>>>(x);

    reduce_kernel<<<dim3(NQT128 * 2, B_), 256>>>(Wv, out);
}

// round 14
// speedup vs baseline: 1.8779x; 1.8779x over previous
#include <cuda_runtime.h>

// Problem constants: B=8, T=4096, C=32 (embedding), D=64 (head)
#define B_  8
#define T_  4096
#define C_  32
#define D_  64
#define NQT128 32            // 128-wide query tiles per batch
#define NCHUNK 8             // k-chunks per query tile (each <=8 k-passes of 64)

typedef unsigned long long ull;

// ---- attn kernel smem layout (floats) ----
#define QP2    132                     // ys row stride (128 q + pad)
#define YS_OFF 0                       // ys[32][132]   = 4224
#define XT_STR (32 * 68)               // one xT buffer = 2176
#define XT_OFF 4224                    // xT[2][32][68] = 4352
#define XN_STR (64 * 36)               // one xN buffer = 2304
#define XN_OFF (XT_OFF + 2 * XT_STR)   // xN[2][64][36] = 4608
#define PS_OFF (XN_OFF + 2 * XN_STR)   // Ps[128][68]   = 8704
#define SM_FLOATS (PS_OFF + 128 * 68)  // 21888 floats = 87552 B

// M = (Wq * Wk^T) * log2(e)  (32x32) — pre-scaled so exp(S) == exp2(S')
__device__ float g_M[C_ * C_];
// split-K partials: slot = ((b*32+qt)*8 + chunk)
__device__ float g_partZ[B_ * NQT128 * NCHUNK * 128 * 32];   // 33.5 MB
__device__ float g_partL[B_ * NQT128 * NCHUNK * 128];

// ---------------------------------------------------------------------------
// packed f32x2 helpers (sm_103a FFMA2 path)
// ---------------------------------------------------------------------------
__device__ __forceinline__ ull pack2(float a, float b) {
    ull r; asm("mov.b64 %0, {%1, %2};" : "=l"(r) : "f"(a), "f"(b)); return r;
}
__device__ __forceinline__ float2 unpack2(ull v) {
    float2 r; asm("mov.b64 {%0, %1}, %2;" : "=f"(r.x), "=f"(r.y) : "l"(v)); return r;
}
__device__ __forceinline__ void fma2(ull& d, ull a, ull b) {
    asm("fma.rn.f32x2 %0, %1, %2, %0;" : "+l"(d) : "l"(a), "l"(b));
}

// ---------------------------------------------------------------------------
// Kernel 0: M = (Wq * Wk^T) * log2(e), conflict-free smem (1 CTA, 256 thr).
// ---------------------------------------------------------------------------
__global__ __launch_bounds__(256) void m_kernel(
    const float* __restrict__ Wk, const float* __restrict__ Wq)
{
    __shared__ float Wqt[64 * 33];
    __shared__ float Wkt[64 * 33];

    const int tid = threadIdx.x;
    const float4* wq = (const float4*)Wq;
    const float4* wk = (const float4*)Wk;
    #pragma unroll
    for (int it = 0; it < 2; it++) {
        int lin = tid + it * 256;            // 0..511: 32 rows x 16 float4
        int r = lin >> 4, d0 = (lin & 15) * 4;
        float4 q4 = wq[lin];
        Wqt[(d0 + 0) * 33 + r] = q4.x;
        Wqt[(d0 + 1) * 33 + r] = q4.y;
        Wqt[(d0 + 2) * 33 + r] = q4.z;
        Wqt[(d0 + 3) * 33 + r] = q4.w;
        float4 k4 = wk[lin];
        Wkt[(d0 + 0) * 33 + r] = k4.x;
        Wkt[(d0 + 1) * 33 + r] = k4.y;
        Wkt[(d0 + 2) * 33 + r] = k4.z;
        Wkt[(d0 + 3) * 33 + r] = k4.w;
    }
    __syncthreads();

    const int i  = tid >> 3;           // 0..31
    const int j0 = (tid & 7) * 4;      // 0,4,..,28
    float a0 = 0.f, a1 = 0.f, a2 = 0.f, a3 = 0.f;
    #pragma unroll 16
    for (int d = 0; d < D_; d++) {
        float qv = Wqt[d * 33 + i];
        const float* wkr = &Wkt[d * 33 + j0];
        a0 += qv * wkr[0];
        a1 += qv * wkr[1];
        a2 += qv * wkr[2];
        a3 += qv * wkr[3];
    }
    const float LOG2E = 1.4426950408889634f;
    g_M[i * C_ + j0 + 0] = a0 * LOG2E;
    g_M[i * C_ + j0 + 1] = a1 * LOG2E;
    g_M[i * C_ + j0 + 2] = a2 * LOG2E;
    g_M[i * C_ + j0 + 3] = a3 * LOG2E;
}

// ---------------------------------------------------------------------------
// Kernel 1: split-K attention partials (R11 structure, proven optimum:
// 2 CTAs/SM, double-buffered x tiles, 2 syncs/pass).
// One CTA = (b, qt, chunk): k-tiles [8*chunk, min(2qt+2, 8*chunk+8)).
//   y = x_q*M (M pre-scaled by log2e);  S' = y x_k^T;  p = exp2(S');
//   Zpart += p x_k;  lpart += rowsum(p)
// ---------------------------------------------------------------------------
__global__ __launch_bounds__(256, 2) void attn_kernel(const float* __restrict__ x)
{
    const int b     = blockIdx.y;
    const int qt    = (NQT128 - 1) - (blockIdx.x >> 3);  // heaviest first
    const int chunk = blockIdx.x & 7;
    const int k0    = chunk * 8;
    const int k1e   = 2 * qt + 2;                        // one past last k-tile
    if (k0 >= k1e) return;                               // empty chunk
    const int k1    = (k1e < k0 + 8) ? k1e : (k0 + 8);

    extern __shared__ float smf[];
    float* ys  = smf + YS_OFF;
    float* xT0 = smf + XT_OFF;
    float* xN0 = smf + XN_OFF;
    float* Ps  = smf + PS_OFF;

    const int tid = threadIdx.x;
    const int tx  = tid & 15, ty = tid >> 4;   // S-pass: 8q x 4k per thread
    const int zr  = tid >> 3;                  // Z-pass rows zr + 32*i
    const int zc  = (tid & 7) * 4;             // Z-pass cols zc..zc+3

    const float* xb = x + b * T_ * C_;

    // ---- stage x_q (128x32) into Ps ----
    {
        const float4* xq = (const float4*)(xb + qt * 128 * C_);
        #pragma unroll
        for (int it = 0; it < 4; it++) {
            int lin = tid + it * 256;
            int r = lin >> 3, c4 = lin & 7;
            *(float4*)&Ps[r * 68 + c4 * 4] = xq[lin];
        }
    }
    __syncthreads();

    // ---- y = x_q * M -> ys (transposed [c'][q]) ----
    {
        const int c0 = tx * 2;
        float a0[8], a1[8];
        #pragma unroll
        for (int i = 0; i < 8; i++) { a0[i] = 0.f; a1[i] = 0.f; }
        #pragma unroll 8
        for (int c = 0; c < C_; c++) {
            float2 m2 = *(const float2*)&g_M[c * C_ + c0];
            #pragma unroll
            for (int i = 0; i < 8; i++) {
                float xv = Ps[(ty * 8 + i) * 68 + c];
                a0[i] += xv * m2.x;
                a1[i] += xv * m2.y;
            }
        }
        #pragma unroll
        for (int i = 0; i < 8; i++) {
            ys[(c0 + 0) * QP2 + ty * 8 + i] = a0[i];
            ys[(c0 + 1) * QP2 + ty * 8 + i] = a1[i];
        }
    }

    // ---- preload k-tile k0 into buffer 0 (natural + transposed) ----
    {
        const float4* xg = (const float4*)(xb + k0 * 64 * C_);
        float4 p0 = xg[tid], p1 = xg[tid + 256];
        int r = tid >> 3, c4 = tid & 7;
        *(float4*)&xN0[r * 36 + c4 * 4] = p0;
        xT0[(c4 * 4 + 0) * 68 + r] = p0.x;
        xT0[(c4 * 4 + 1) * 68 + r] = p0.y;
        xT0[(c4 * 4 + 2) * 68 + r] = p0.z;
        xT0[(c4 * 4 + 3) * 68 + r] = p0.w;
        int r2 = r + 32;
        *(float4*)&xN0[r2 * 36 + c4 * 4] = p1;
        xT0[(c4 * 4 + 0) * 68 + r2] = p1.x;
        xT0[(c4 * 4 + 1) * 68 + r2] = p1.y;
        xT0[(c4 * 4 + 2) * 68 + r2] = p1.z;
        xT0[(c4 * 4 + 3) * 68 + r2] = p1.w;
    }

    float l_i[8];
    #pragma unroll
    for (int i = 0; i < 8; i++) l_i[i] = 0.f;
    ull z2[4][2];
    #pragma unroll
    for (int i = 0; i < 4; i++) { z2[i][0] = 0ull; z2[i][1] = 0ull; }

    for (int kt = k0; kt < k1; kt++) {
        const int buf = (kt - k0) & 1;
        const float* xTb = xT0 + buf * XT_STR;
        const float* xNb = xN0 + buf * XN_STR;

        __syncthreads();   // (A) this buf loaded; prior Z-pass done; ys ready

        // prefetch next k-tile into registers (stored after S-pass)
        float4 p0, p1;
        const bool pf = (kt + 1 < k1);
        if (pf) {
            const float4* xg = (const float4*)(xb + (kt + 1) * 64 * C_);
            p0 = xg[tid]; p1 = xg[tid + 256];
        }

        // ---- S' = y * x_k^T : 8q x 4k, q-paired FFMA2, pair-free q loads ----
        ull s2[4][4];   // [k-col j][q-pair i2]
        #pragma unroll
        for (int j = 0; j < 4; j++)
            #pragma unroll
            for (int i2 = 0; i2 < 4; i2++) s2[j][i2] = 0ull;

        #pragma unroll 8
        for (int c = 0; c < C_; c++) {
            ulonglong2 qa = *(const ulonglong2*)&ys[c * QP2 + ty * 8];
            ulonglong2 qb = *(const ulonglong2*)&ys[c * QP2 + ty * 8 + 4];
            float4 kv = *(const float4*)&xTb[c * 68 + tx * 4];
            ull kd[4] = { pack2(kv.x, kv.x), pack2(kv.y, kv.y),
                          pack2(kv.z, kv.z), pack2(kv.w, kv.w) };
            #pragma unroll
            for (int j = 0; j < 4; j++) {
                fma2(s2[j][0], qa.x, kd[j]);
                fma2(s2[j][1], qa.y, kd[j]);
                fma2(s2[j][2], qb.x, kd[j]);
                fma2(s2[j][3], qb.y, kd[j]);
            }
        }

        float s[8][4];
        #pragma unroll
        for (int j = 0; j < 4; j++)
            #pragma unroll
            for (int i2 = 0; i2 < 4; i2++) {
                float2 u = unpack2(s2[j][i2]);
                s[2 * i2 + 0][j] = u.x;
                s[2 * i2 + 1][j] = u.y;
            }

        if (kt >= 2 * qt) {   // causal mask (last two k-tiles of this qt)
            const int koff = (kt - 2 * qt) * 64;
            #pragma unroll
            for (int i = 0; i < 8; i++)
                #pragma unroll
                for (int j = 0; j < 4; j++)
                    if (koff + tx * 4 + j > ty * 8 + i) s[i][j] = -1e30f;
        }

        // ---- store prefetched tile into other buffer ----
        if (pf) {
            const int nb = buf ^ 1;
            float* xNn = xN0 + nb * XN_STR;
            float* xTn = xT0 + nb * XT_STR;
            int r = tid >> 3, c4 = tid & 7;
            *(float4*)&xNn[r * 36 + c4 * 4] = p0;
            xTn[(c4 * 4 + 0) * 68 + r] = p0.x;
            xTn[(c4 * 4 + 1) * 68 + r] = p0.y;
            xTn[(c4 * 4 + 2) * 68 + r] = p0.z;
            xTn[(c4 * 4 + 3) * 68 + r] = p0.w;
            int r2 = r + 32;
            *(float4*)&xNn[r2 * 36 + c4 * 4] = p1;
            xTn[(c4 * 4 + 0) * 68 + r2] = p1.x;
            xTn[(c4 * 4 + 1) * 68 + r2] = p1.y;
            xTn[(c4 * 4 + 2) * 68 + r2] = p1.z;
            xTn[(c4 * 4 + 3) * 68 + r2] = p1.w;
        }

        // ---- p = exp2(s') (M pre-scaled by log2e), local row-sum ----
        #pragma unroll
        for (int i = 0; i < 8; i++) {
            float e0 = exp2f(s[i][0]);
            float e1 = exp2f(s[i][1]);
            float e2 = exp2f(s[i][2]);
            float e3 = exp2f(s[i][3]);
            l_i[i] += (e0 + e1) + (e2 + e3);
            *(float4*)&Ps[(ty * 8 + i) * 68 + tx * 4] = make_float4(e0, e1, e2, e3);
        }
        __syncthreads();   // (B) Ps visible

        // ---- Z += P * x_k : rows zr+32i, cols zc..zc+3, c-paired FFMA2 ----
        #pragma unroll 4
        for (int k4 = 0; k4 < 16; k4++) {
            ulonglong2 xp[4];
            float4 pr[4];
            #pragma unroll
            for (int kk = 0; kk < 4; kk++)
                xp[kk] = *(const ulonglong2*)&xNb[(k4 * 4 + kk) * 36 + zc];
            #pragma unroll
            for (int i = 0; i < 4; i++)
                pr[i] = *(const float4*)&Ps[(zr + 32 * i) * 68 + k4 * 4];

            #pragma unroll
            for (int i = 0; i < 4; i++) {
                const float* pv = (const float*)&pr[i];
                #pragma unroll
                for (int kk = 0; kk < 4; kk++) {
                    ull pd = pack2(pv[kk], pv[kk]);
                    fma2(z2[i][0], pd, xp[kk].x);
                    fma2(z2[i][1], pd, xp[kk].y);
                }
            }
        }
    }

    // ---- write partials ----
    const int islot = (b * NQT128 + qt) * NCHUNK + chunk;

    #pragma unroll
    for (int i = 0; i < 8; i++) {   // partial row sums (reduced over tx)
        float rs = l_i[i];
        rs += __shfl_xor_sync(0xffffffffu, rs, 8);
        rs += __shfl_xor_sync(0xffffffffu, rs, 4);
        rs += __shfl_xor_sync(0xffffffffu, rs, 2);
        rs += __shfl_xor_sync(0xffffffffu, rs, 1);
        if (tx == 0) g_partL[islot * 128 + ty * 8 + i] = rs;
    }

    float* zp = g_partZ + islot * (128 * 32);
    #pragma unroll
    for (int i = 0; i < 4; i++) {
        float2 a = unpack2(z2[i][0]);
        float2 c = unpack2(z2[i][1]);
        *(float4*)&zp[(zr + 32 * i) * 32 + zc] = make_float4(a.x, a.y, c.x, c.y);
    }
}

// ---------------------------------------------------------------------------
// Kernel 2: reduce partials, out = (Z / l) * Wv.
// One CTA = (b, qt, quarter): 32 q-rows.  1024 CTAs for latency hiding.
// ---------------------------------------------------------------------------
__global__ __launch_bounds__(256) void reduce_kernel(
    const float* __restrict__ Wv, float* __restrict__ out)
{
    __shared__ float Zs[32][36];
    __shared__ float Wvs[32][68];
    __shared__ float lv[32];

    const int qt   = blockIdx.x >> 2;
    const int quad = blockIdx.x & 3;
    const int b    = blockIdx.y;
    const int tid  = threadIdx.x;
    const int nc   = (2 * qt + 1) / 8 + 1;   // valid chunks for this qt
    const int base = (b * NQT128 + qt) * NCHUNK;
    const int row0 = quad * 32;

    // sum partial Z for rows row0..row0+31 (each thread: 1 float4)
    float4 acc = make_float4(0.f, 0.f, 0.f, 0.f);
    for (int s = 0; s < nc; s++) {
        const float4* zp = (const float4*)(g_partZ + (base + s) * (128 * 32) + row0 * 32);
        float4 v = zp[tid];
        acc.x += v.x; acc.y += v.y; acc.z += v.z; acc.w += v.w;
    }
    // sum partial l
    if (tid < 32) {
        float ls = 0.f;
        for (int s = 0; s < nc; s++)
            ls += g_partL[(base + s) * 128 + row0 + tid];
        lv[tid] = 1.f / ls;
    }
    __syncthreads();

    // stage Z scaled by 1/l
    {
        int r = tid >> 3, c4 = tid & 7;
        float li = lv[r];
        *(float4*)&Zs[r][c4 * 4] = make_float4(acc.x * li, acc.y * li,
                                               acc.z * li, acc.w * li);
    }
    {
        const float4* wg = (const float4*)Wv;
        #pragma unroll
        for (int it = 0; it < 2; it++) {
            int lin = tid + it * 256;
            int r = lin >> 4, c4 = lin & 15;
            *(float4*)&Wvs[r][c4 * 4] = wg[lin];
        }
    }
    __syncthreads();

    // out = Z * Wv : rows ty, ty+16; cols tx*4..+3
    const int tx = tid & 15, ty = tid >> 4;
    float o[2][4];
    #pragma unroll
    for (int i = 0; i < 2; i++)
        #pragma unroll
        for (int j = 0; j < 4; j++) o[i][j] = 0.f;

    #pragma unroll 4
    for (int c = 0; c < C_; c++) {
        float4 w4 = *(const float4*)&Wvs[c][tx * 4];
        #pragma unroll
        for (int i = 0; i < 2; i++) {
            float zv = Zs[ty + 16 * i][c];
            o[i][0] += zv * w4.x; o[i][1] += zv * w4.y;
            o[i][2] += zv * w4.z; o[i][3] += zv * w4.w;
        }
    }

    float* Og = out + (b * T_ + qt * 128 + row0) * D_;
    #pragma unroll
    for (int i = 0; i < 2; i++)
        *(float4*)&Og[(ty + 16 * i) * D_ + tx * 4] =
            make_float4(o[i][0], o[i][1], o[i][2], o[i][3]);
}

// ---------------------------------------------------------------------------
extern "C" void kernel_launch(void* const* d_in, const int* in_sizes, int n_in,
                              void* d_out, int out_size)
{
    const float* x  = (const float*)d_in[0];
    const float* Wk = (const float*)d_in[1];
    const float* Wq = (const float*)d_in[2];
    const float* Wv = (const float*)d_in[3];
    float* out = (float*)d_out;

    m_kernel<<<1, 256>>>(Wk, Wq);

    const int smem = SM_FLOATS * (int)sizeof(float);   // 87552 B
    cudaFuncSetAttribute(attn_kernel, cudaFuncAttributeMaxDynamicSharedMemorySize, smem);
    attn_kernel<<<dim3(NQT128 * NCHUNK, B_), 256, smem>>>(x);

    reduce_kernel<<<dim3(NQT128 * 4, B_), 256>>>(Wv, out);
}

// round 15
// speedup vs baseline: 1.9054x; 1.0146x over previous
#include <cuda_runtime.h>

// Problem constants: B=8, T=4096, C=32 (embedding), D=64 (head)
#define B_  8
#define T_  4096
#define C_  32
#define D_  64
#define NQT128 32            // 128-wide query tiles per batch
#define NCHUNK 8             // k-chunks per query tile (each <=8 k-passes of 64)

typedef unsigned long long ull;

// ---- attn kernel smem layout (floats) ----
#define QP2    132                     // ys row stride (128 q + pad)
#define YS_OFF 0                       // ys[32][132]   = 4224
#define XT_STR (32 * 68)               // one xT buffer = 2176
#define XT_OFF 4224                    // xT[2][32][68] = 4352
#define XN_STR (64 * 36)               // one xN buffer = 2304
#define XN_OFF (XT_OFF + 2 * XT_STR)   // xN[2][64][36] = 4608
#define PS_OFF (XN_OFF + 2 * XN_STR)   // Ps[128][68]   = 8704
#define SM_FLOATS (PS_OFF + 128 * 68)  // 21888 floats = 87552 B

// M = (Wq * Wk^T) * log2(e)  (32x32) — pre-scaled so exp(S) == ex2(S')
__device__ float g_M[C_ * C_];
// split-K partials: slot = ((b*32+qt)*8 + chunk)
__device__ float g_partZ[B_ * NQT128 * NCHUNK * 128 * 32];   // 33.5 MB
__device__ float g_partL[B_ * NQT128 * NCHUNK * 128];

// ---------------------------------------------------------------------------
// packed f32x2 + fast-exp2 helpers
// ---------------------------------------------------------------------------
__device__ __forceinline__ ull pack2(float a, float b) {
    ull r; asm("mov.b64 %0, {%1, %2};" : "=l"(r) : "f"(a), "f"(b)); return r;
}
__device__ __forceinline__ float2 unpack2(ull v) {
    float2 r; asm("mov.b64 {%0, %1}, %2;" : "=f"(r.x), "=f"(r.y) : "l"(v)); return r;
}
__device__ __forceinline__ void fma2(ull& d, ull a, ull b) {
    asm("fma.rn.f32x2 %0, %1, %2, %0;" : "+l"(d) : "l"(a), "l"(b));
}
// hardware MUFU.EX2 — the same op __expf lowers to (after its log2e FMUL,
// which we've baked into M).  NOT exp2f(), which is the slow precise routine.
__device__ __forceinline__ float ex2(float x) {
    float r; asm("ex2.approx.f32 %0, %1;" : "=f"(r) : "f"(x)); return r;
}

// ---------------------------------------------------------------------------
// Kernel 0: M = (Wq * Wk^T) * log2(e), conflict-free smem (1 CTA, 256 thr).
// ---------------------------------------------------------------------------
__global__ __launch_bounds__(256) void m_kernel(
    const float* __restrict__ Wk, const float* __restrict__ Wq)
{
    __shared__ float Wqt[64 * 33];
    __shared__ float Wkt[64 * 33];

    const int tid = threadIdx.x;
    const float4* wq = (const float4*)Wq;
    const float4* wk = (const float4*)Wk;
    #pragma unroll
    for (int it = 0; it < 2; it++) {
        int lin = tid + it * 256;            // 0..511: 32 rows x 16 float4
        int r = lin >> 4, d0 = (lin & 15) * 4;
        float4 q4 = wq[lin];
        Wqt[(d0 + 0) * 33 + r] = q4.x;
        Wqt[(d0 + 1) * 33 + r] = q4.y;
        Wqt[(d0 + 2) * 33 + r] = q4.z;
        Wqt[(d0 + 3) * 33 + r] = q4.w;
        float4 k4 = wk[lin];
        Wkt[(d0 + 0) * 33 + r] = k4.x;
        Wkt[(d0 + 1) * 33 + r] = k4.y;
        Wkt[(d0 + 2) * 33 + r] = k4.z;
        Wkt[(d0 + 3) * 33 + r] = k4.w;
    }
    __syncthreads();

    const int i  = tid >> 3;           // 0..31
    const int j0 = (tid & 7) * 4;      // 0,4,..,28
    float a0 = 0.f, a1 = 0.f, a2 = 0.f, a3 = 0.f;
    #pragma unroll 16
    for (int d = 0; d < D_; d++) {
        float qv = Wqt[d * 33 + i];
        const float* wkr = &Wkt[d * 33 + j0];
        a0 += qv * wkr[0];
        a1 += qv * wkr[1];
        a2 += qv * wkr[2];
        a3 += qv * wkr[3];
    }
    const float LOG2E = 1.4426950408889634f;
    g_M[i * C_ + j0 + 0] = a0 * LOG2E;
    g_M[i * C_ + j0 + 1] = a1 * LOG2E;
    g_M[i * C_ + j0 + 2] = a2 * LOG2E;
    g_M[i * C_ + j0 + 3] = a3 * LOG2E;
}

// ---------------------------------------------------------------------------
// Kernel 1: split-K attention partials (R11 structure, proven optimum:
// 2 CTAs/SM, double-buffered x tiles, 2 syncs/pass).
// One CTA = (b, qt, chunk): k-tiles [8*chunk, min(2qt+2, 8*chunk+8)).
//   y = x_q*M (log2e baked in);  S' = y x_k^T;  p = ex2(S');
//   Zpart += p x_k;  lpart += rowsum(p)
// ---------------------------------------------------------------------------
__global__ __launch_bounds__(256, 2) void attn_kernel(const float* __restrict__ x)
{
    const int b     = blockIdx.y;
    const int qt    = (NQT128 - 1) - (blockIdx.x >> 3);  // heaviest first
    const int chunk = blockIdx.x & 7;
    const int k0    = chunk * 8;
    const int k1e   = 2 * qt + 2;                        // one past last k-tile
    if (k0 >= k1e) return;                               // empty chunk
    const int k1    = (k1e < k0 + 8) ? k1e : (k0 + 8);

    extern __shared__ float smf[];
    float* ys  = smf + YS_OFF;
    float* xT0 = smf + XT_OFF;
    float* xN0 = smf + XN_OFF;
    float* Ps  = smf + PS_OFF;

    const int tid = threadIdx.x;
    const int tx  = tid & 15, ty = tid >> 4;   // S-pass: 8q x 4k per thread
    const int zr  = tid >> 3;                  // Z-pass rows zr + 32*i
    const int zc  = (tid & 7) * 4;             // Z-pass cols zc..zc+3

    const float* xb = x + b * T_ * C_;

    // ---- stage x_q (128x32) into Ps ----
    {
        const float4* xq = (const float4*)(xb + qt * 128 * C_);
        #pragma unroll
        for (int it = 0; it < 4; it++) {
            int lin = tid + it * 256;
            int r = lin >> 3, c4 = lin & 7;
            *(float4*)&Ps[r * 68 + c4 * 4] = xq[lin];
        }
    }
    __syncthreads();

    // ---- y = x_q * M -> ys (transposed [c'][q]) ----
    {
        const int c0 = tx * 2;
        float a0[8], a1[8];
        #pragma unroll
        for (int i = 0; i < 8; i++) { a0[i] = 0.f; a1[i] = 0.f; }
        #pragma unroll 8
        for (int c = 0; c < C_; c++) {
            float2 m2 = *(const float2*)&g_M[c * C_ + c0];
            #pragma unroll
            for (int i = 0; i < 8; i++) {
                float xv = Ps[(ty * 8 + i) * 68 + c];
                a0[i] += xv * m2.x;
                a1[i] += xv * m2.y;
            }
        }
        #pragma unroll
        for (int i = 0; i < 8; i++) {
            ys[(c0 + 0) * QP2 + ty * 8 + i] = a0[i];
            ys[(c0 + 1) * QP2 + ty * 8 + i] = a1[i];
        }
    }

    // ---- preload k-tile k0 into buffer 0 (natural + transposed) ----
    {
        const float4* xg = (const float4*)(xb + k0 * 64 * C_);
        float4 p0 = xg[tid], p1 = xg[tid + 256];
        int r = tid >> 3, c4 = tid & 7;
        *(float4*)&xN0[r * 36 + c4 * 4] = p0;
        xT0[(c4 * 4 + 0) * 68 + r] = p0.x;
        xT0[(c4 * 4 + 1) * 68 + r] = p0.y;
        xT0[(c4 * 4 + 2) * 68 + r] = p0.z;
        xT0[(c4 * 4 + 3) * 68 + r] = p0.w;
        int r2 = r + 32;
        *(float4*)&xN0[r2 * 36 + c4 * 4] = p1;
        xT0[(c4 * 4 + 0) * 68 + r2] = p1.x;
        xT0[(c4 * 4 + 1) * 68 + r2] = p1.y;
        xT0[(c4 * 4 + 2) * 68 + r2] = p1.z;
        xT0[(c4 * 4 + 3) * 68 + r2] = p1.w;
    }

    float l_i[8];
    #pragma unroll
    for (int i = 0; i < 8; i++) l_i[i] = 0.f;
    ull z2[4][2];
    #pragma unroll
    for (int i = 0; i < 4; i++) { z2[i][0] = 0ull; z2[i][1] = 0ull; }

    for (int kt = k0; kt < k1; kt++) {
        const int buf = (kt - k0) & 1;
        const float* xTb = xT0 + buf * XT_STR;
        const float* xNb = xN0 + buf * XN_STR;

        __syncthreads();   // (A) this buf loaded; prior Z-pass done; ys ready

        // prefetch next k-tile into registers (stored after S-pass)
        float4 p0, p1;
        const bool pf = (kt + 1 < k1);
        if (pf) {
            const float4* xg = (const float4*)(xb + (kt + 1) * 64 * C_);
            p0 = xg[tid]; p1 = xg[tid + 256];
        }

        // ---- S' = y * x_k^T : 8q x 4k, q-paired FFMA2, pair-free q loads ----
        ull s2[4][4];   // [k-col j][q-pair i2]
        #pragma unroll
        for (int j = 0; j < 4; j++)
            #pragma unroll
            for (int i2 = 0; i2 < 4; i2++) s2[j][i2] = 0ull;

        #pragma unroll 8
        for (int c = 0; c < C_; c++) {
            ulonglong2 qa = *(const ulonglong2*)&ys[c * QP2 + ty * 8];
            ulonglong2 qb = *(const ulonglong2*)&ys[c * QP2 + ty * 8 + 4];
            float4 kv = *(const float4*)&xTb[c * 68 + tx * 4];
            ull kd[4] = { pack2(kv.x, kv.x), pack2(kv.y, kv.y),
                          pack2(kv.z, kv.z), pack2(kv.w, kv.w) };
            #pragma unroll
            for (int j = 0; j < 4; j++) {
                fma2(s2[j][0], qa.x, kd[j]);
                fma2(s2[j][1], qa.y, kd[j]);
                fma2(s2[j][2], qb.x, kd[j]);
                fma2(s2[j][3], qb.y, kd[j]);
            }
        }

        float s[8][4];
        #pragma unroll
        for (int j = 0; j < 4; j++)
            #pragma unroll
            for (int i2 = 0; i2 < 4; i2++) {
                float2 u = unpack2(s2[j][i2]);
                s[2 * i2 + 0][j] = u.x;
                s[2 * i2 + 1][j] = u.y;
            }

        if (kt >= 2 * qt) {   // causal mask (last two k-tiles of this qt)
            const int koff = (kt - 2 * qt) * 64;
            #pragma unroll
            for (int i = 0; i < 8; i++)
                #pragma unroll
                for (int j = 0; j < 4; j++)
                    if (koff + tx * 4 + j > ty * 8 + i) s[i][j] = -1e30f;
        }

        // ---- store prefetched tile into other buffer ----
        if (pf) {
            const int nb = buf ^ 1;
            float* xNn = xN0 + nb * XN_STR;
            float* xTn = xT0 + nb * XT_STR;
            int r = tid >> 3, c4 = tid & 7;
            *(float4*)&xNn[r * 36 + c4 * 4] = p0;
            xTn[(c4 * 4 + 0) * 68 + r] = p0.x;
            xTn[(c4 * 4 + 1) * 68 + r] = p0.y;
            xTn[(c4 * 4 + 2) * 68 + r] = p0.z;
            xTn[(c4 * 4 + 3) * 68 + r] = p0.w;
            int r2 = r + 32;
            *(float4*)&xNn[r2 * 36 + c4 * 4] = p1;
            xTn[(c4 * 4 + 0) * 68 + r2] = p1.x;
            xTn[(c4 * 4 + 1) * 68 + r2] = p1.y;
            xTn[(c4 * 4 + 2) * 68 + r2] = p1.z;
            xTn[(c4 * 4 + 3) * 68 + r2] = p1.w;
        }

        // ---- p = ex2(s') (MUFU.EX2; log2e baked into M), local row-sum ----
        #pragma unroll
        for (int i = 0; i < 8; i++) {
            float e0 = ex2(s[i][0]);
            float e1 = ex2(s[i][1]);
            float e2 = ex2(s[i][2]);
            float e3 = ex2(s[i][3]);
            l_i[i] += (e0 + e1) + (e2 + e3);
            *(float4*)&Ps[(ty * 8 + i) * 68 + tx * 4] = make_float4(e0, e1, e2, e3);
        }
        __syncthreads();   // (B) Ps visible

        // ---- Z += P * x_k : rows zr+32i, cols zc..zc+3, c-paired FFMA2 ----
        #pragma unroll 4
        for (int k4 = 0; k4 < 16; k4++) {
            ulonglong2 xp[4];
            float4 pr[4];
            #pragma unroll
            for (int kk = 0; kk < 4; kk++)
                xp[kk] = *(const ulonglong2*)&xNb[(k4 * 4 + kk) * 36 + zc];
            #pragma unroll
            for (int i = 0; i < 4; i++)
                pr[i] = *(const float4*)&Ps[(zr + 32 * i) * 68 + k4 * 4];

            #pragma unroll
            for (int i = 0; i < 4; i++) {
                const float* pv = (const float*)&pr[i];
                #pragma unroll
                for (int kk = 0; kk < 4; kk++) {
                    ull pd = pack2(pv[kk], pv[kk]);
                    fma2(z2[i][0], pd, xp[kk].x);
                    fma2(z2[i][1], pd, xp[kk].y);
                }
            }
        }
    }

    // ---- write partials ----
    const int islot = (b * NQT128 + qt) * NCHUNK + chunk;

    #pragma unroll
    for (int i = 0; i < 8; i++) {   // partial row sums (reduced over tx)
        float rs = l_i[i];
        rs += __shfl_xor_sync(0xffffffffu, rs, 8);
        rs += __shfl_xor_sync(0xffffffffu, rs, 4);
        rs += __shfl_xor_sync(0xffffffffu, rs, 2);
        rs += __shfl_xor_sync(0xffffffffu, rs, 1);
        if (tx == 0) g_partL[islot * 128 + ty * 8 + i] = rs;
    }

    float* zp = g_partZ + islot * (128 * 32);
    #pragma unroll
    for (int i = 0; i < 4; i++) {
        float2 a = unpack2(z2[i][0]);
        float2 c = unpack2(z2[i][1]);
        *(float4*)&zp[(zr + 32 * i) * 32 + zc] = make_float4(a.x, a.y, c.x, c.y);
    }
}

// ---------------------------------------------------------------------------
// Kernel 2: reduce partials, out = (Z / l) * Wv.
// One CTA = (b, qt, half): 64 q-rows.  512 CTAs (proven config).
// ---------------------------------------------------------------------------
__global__ __launch_bounds__(256) void reduce_kernel(
    const float* __restrict__ Wv, float* __restrict__ out)
{
    __shared__ float Zs[64][36];
    __shared__ float Wvs[32][68];
    __shared__ float lv[64];

    const int qt   = blockIdx.x >> 1;
    const int half = blockIdx.x & 1;
    const int b    = blockIdx.y;
    const int tid  = threadIdx.x;
    const int nc   = (2 * qt + 1) / 8 + 1;   // valid chunks for this qt
    const int base = (b * NQT128 + qt) * NCHUNK;
    const int row0 = half * 64;

    float4 acc[2];
    #pragma unroll
    for (int it = 0; it < 2; it++) acc[it] = make_float4(0.f, 0.f, 0.f, 0.f);
    for (int s = 0; s < nc; s++) {
        const float4* zp = (const float4*)(g_partZ + (base + s) * (128 * 32) + row0 * 32);
        #pragma unroll
        for (int it = 0; it < 2; it++) {
            float4 v = zp[tid + it * 256];
            acc[it].x += v.x; acc[it].y += v.y; acc[it].z += v.z; acc[it].w += v.w;
        }
    }
    if (tid < 64) {
        float ls = 0.f;
        for (int s = 0; s < nc; s++)
            ls += g_partL[(base + s) * 128 + row0 + tid];
        lv[tid] = 1.f / ls;
    }
    __syncthreads();

    #pragma unroll
    for (int it = 0; it < 2; it++) {
        int lin = tid + it * 256;
        int r = lin >> 3, c4 = lin & 7;
        float li = lv[r];
        *(float4*)&Zs[r][c4 * 4] = make_float4(acc[it].x * li, acc[it].y * li,
                                               acc[it].z * li, acc[it].w * li);
    }
    {
        const float4* wg = (const float4*)Wv;
        #pragma unroll
        for (int it = 0; it < 2; it++) {
            int lin = tid + it * 256;
            int r = lin >> 4, c4 = lin & 15;
            *(float4*)&Wvs[r][c4 * 4] = wg[lin];
        }
    }
    __syncthreads();

    const int tx = tid & 15, ty = tid >> 4;
    float o[4][4];
    #pragma unroll
    for (int i = 0; i < 4; i++)
        #pragma unroll
        for (int j = 0; j < 4; j++) o[i][j] = 0.f;

    #pragma unroll 4
    for (int c = 0; c < C_; c++) {
        float4 w4 = *(const float4*)&Wvs[c][tx * 4];
        #pragma unroll
        for (int i = 0; i < 4; i++) {
            float zv = Zs[ty + 16 * i][c];
            o[i][0] += zv * w4.x; o[i][1] += zv * w4.y;
            o[i][2] += zv * w4.z; o[i][3] += zv * w4.w;
        }
    }

    float* Og = out + (b * T_ + qt * 128 + row0) * D_;
    #pragma unroll
    for (int i = 0; i < 4; i++)
        *(float4*)&Og[(ty + 16 * i) * D_ + tx * 4] =
            make_float4(o[i][0], o[i][1], o[i][2], o[i][3]);
}

// ---------------------------------------------------------------------------
extern "C" void kernel_launch(void* const* d_in, const int* in_sizes, int n_in,
                              void* d_out, int out_size)
{
    const float* x  = (const float*)d_in[0];
    const float* Wk = (const float*)d_in[1];
    const float* Wq = (const float*)d_in[2];
    const float* Wv = (const float*)d_in[3];
    float* out = (float*)d_out;

    m_kernel<<<1, 256>>>(Wk, Wq);

    const int smem = SM_FLOATS * (int)sizeof(float);   // 87552 B
    cudaFuncSetAttribute(attn_kernel, cudaFuncAttributeMaxDynamicSharedMemorySize, smem);
    attn_kernel<<<dim3(NQT128 * NCHUNK, B_), 256, smem>>>(x);

    reduce_kernel<<<dim3(NQT128 * 2, B_), 256>>>(Wv, out);
}

// round 16
// speedup vs baseline: 2.0118x; 1.0558x over previous
#include <cuda_runtime.h>

// Problem constants: B=8, T=4096, C=32 (embedding), D=64 (head)
#define B_  8
#define T_  4096
#define C_  32
#define D_  64
#define NQT128 32            // 128-wide query tiles per batch
#define NCHUNK 16            // k-chunks per query tile (each <=4 k-passes of 64)
#define CHUNKP 4             // k-passes per chunk

typedef unsigned long long ull;

// ---- attn kernel smem layout (floats) ----
#define QP2    132                     // ys row stride (128 q + pad)
#define YS_OFF 0                       // ys[32][132]   = 4224
#define XT_STR (32 * 68)               // one xT buffer = 2176
#define XT_OFF 4224                    // xT[2][32][68] = 4352
#define XN_STR (64 * 36)               // one xN buffer = 2304
#define XN_OFF (XT_OFF + 2 * XT_STR)   // xN[2][64][36] = 4608
#define PS_OFF (XN_OFF + 2 * XN_STR)   // Ps[128][68]   = 8704
#define SM_FLOATS (PS_OFF + 128 * 68)  // 21888 floats = 87552 B

// y = x * (Wq Wk^T)  [B*T, 32]
__device__ float g_y[B_ * T_ * C_];
// split-K partials: slot = ((b*32+qt)*16 + chunk)
__device__ float g_partZ[B_ * NQT128 * NCHUNK * 128 * 32];   // 67 MB
__device__ float g_partL[B_ * NQT128 * NCHUNK * 128];

// ---------------------------------------------------------------------------
// packed f32x2 helpers (sm_103a FFMA2 path)
// ---------------------------------------------------------------------------
__device__ __forceinline__ ull pack2(float a, float b) {
    ull r; asm("mov.b64 %0, {%1, %2};" : "=l"(r) : "f"(a), "f"(b)); return r;
}
__device__ __forceinline__ float2 unpack2(ull v) {
    float2 r; asm("mov.b64 {%0, %1}, %2;" : "=f"(r.x), "=f"(r.y) : "l"(v)); return r;
}
__device__ __forceinline__ void fma2(ull& d, ull a, ull b) {
    asm("fma.rn.f32x2 %0, %1, %2, %0;" : "+l"(d) : "l"(a), "l"(b));
}

// ---------------------------------------------------------------------------
// Kernel 0: y = x * (Wq Wk^T).  One CTA = 128 rows; M computed per-CTA from
// conflict-free transposed-staged weights (R13-proven, ~14.5us at 256 CTAs).
// ---------------------------------------------------------------------------
__global__ __launch_bounds__(256) void y_kernel(
    const float* __restrict__ x, const float* __restrict__ Wk,
    const float* __restrict__ Wq)
{
    __shared__ float Wqt[64 * 33];
    __shared__ float Wkt[64 * 33];
    __shared__ float Ms[32 * 34];
    __shared__ float xs[128 * 36];
    __shared__ float ysb[128 * 36];

    const int tid  = threadIdx.x;
    const int row0 = blockIdx.x * 128;

    {
        const float4* wq = (const float4*)Wq;
        const float4* wk = (const float4*)Wk;
        #pragma unroll
        for (int it = 0; it < 2; it++) {
            int lin = tid + it * 256;            // 0..511: 32 rows x 16 float4
            int r = lin >> 4, d0 = (lin & 15) * 4;
            float4 q4 = wq[lin];
            Wqt[(d0 + 0) * 33 + r] = q4.x;
            Wqt[(d0 + 1) * 33 + r] = q4.y;
            Wqt[(d0 + 2) * 33 + r] = q4.z;
            Wqt[(d0 + 3) * 33 + r] = q4.w;
            float4 k4 = wk[lin];
            Wkt[(d0 + 0) * 33 + r] = k4.x;
            Wkt[(d0 + 1) * 33 + r] = k4.y;
            Wkt[(d0 + 2) * 33 + r] = k4.z;
            Wkt[(d0 + 3) * 33 + r] = k4.w;
        }
        const float4* xg = (const float4*)(x + row0 * C_);
        #pragma unroll
        for (int it = 0; it < 4; it++) {
            int lin = tid + it * 256;            // 0..1023
            int r = lin >> 3, c4 = lin & 7;
            *(float4*)&xs[r * 36 + c4 * 4] = xg[lin];
        }
    }
    __syncthreads();

    // M[i][j] = dot(Wq row i, Wk row j) — conflict-free
    {
        const int i  = tid >> 3;
        const int j0 = (tid & 7) * 4;
        float a0 = 0.f, a1 = 0.f, a2 = 0.f, a3 = 0.f;
        #pragma unroll 16
        for (int d = 0; d < D_; d++) {
            float qv = Wqt[d * 33 + i];
            const float* wkr = &Wkt[d * 33 + j0];
            a0 += qv * wkr[0];
            a1 += qv * wkr[1];
            a2 += qv * wkr[2];
            a3 += qv * wkr[3];
        }
        Ms[i * 34 + j0 + 0] = a0;
        Ms[i * 34 + j0 + 1] = a1;
        Ms[i * 34 + j0 + 2] = a2;
        Ms[i * 34 + j0 + 3] = a3;
    }
    __syncthreads();

    // y-tile = xs * M
    {
        const int tx = tid & 15, ty = tid >> 4;
        const int c0 = tx * 2;
        float a0[8], a1[8];
        #pragma unroll
        for (int i = 0; i < 8; i++) { a0[i] = 0.f; a1[i] = 0.f; }
        #pragma unroll 8
        for (int c = 0; c < C_; c++) {
            float2 m2 = *(const float2*)&Ms[c * 34 + c0];
            #pragma unroll
            for (int i = 0; i < 8; i++) {
                float xv = xs[(ty * 8 + i) * 36 + c];
                a0[i] += xv * m2.x;
                a1[i] += xv * m2.y;
            }
        }
        #pragma unroll
        for (int i = 0; i < 8; i++) {
            ysb[(ty * 8 + i) * 36 + c0 + 0] = a0[i];
            ysb[(ty * 8 + i) * 36 + c0 + 1] = a1[i];
        }
    }
    __syncthreads();

    {
        float4* yg = (float4*)(g_y + row0 * C_);
        #pragma unroll
        for (int it = 0; it < 4; it++) {
            int lin = tid + it * 256;
            int r = lin >> 3, c4 = lin & 7;
            yg[lin] = *(const float4*)&ysb[r * 36 + c4 * 4];
        }
    }
}

// ---------------------------------------------------------------------------
// Kernel 1: split-K attention partials.  Mainloop byte-identical to the
// proven 212us R11 kernel; prologue = transposed y-tile load (y precomputed);
// NCHUNK=16 (<=4 passes/chunk) for finer last-wave balance.
// One CTA = (b, qt, chunk): k-tiles [4*chunk, min(2qt+2, 4*chunk+4)).
// ---------------------------------------------------------------------------
__global__ __launch_bounds__(256, 2) void attn_kernel(const float* __restrict__ x)
{
    const int b     = blockIdx.y;
    const int qt    = (NQT128 - 1) - (blockIdx.x >> 4);  // heaviest first
    const int chunk = blockIdx.x & 15;
    const int k0    = chunk * CHUNKP;
    const int k1e   = 2 * qt + 2;                        // one past last k-tile
    if (k0 >= k1e) return;                               // empty chunk
    const int k1    = (k1e < k0 + CHUNKP) ? k1e : (k0 + CHUNKP);

    extern __shared__ float smf[];
    float* ys  = smf + YS_OFF;
    float* xT0 = smf + XT_OFF;
    float* xN0 = smf + XN_OFF;
    float* Ps  = smf + PS_OFF;

    const int tid = threadIdx.x;
    const int tx  = tid & 15, ty = tid >> 4;   // S-pass: 8q x 4k per thread
    const int zr  = tid >> 3;                  // Z-pass rows zr + 32*i
    const int zc  = (tid & 7) * 4;             // Z-pass cols zc..zc+3

    const float* xb = x + b * T_ * C_;

    // ---- load y tile (128x32) transposed into ys[c][q] ----
    {
        const float4* yq = (const float4*)(g_y + (b * T_ + qt * 128) * C_);
        #pragma unroll
        for (int it = 0; it < 4; it++) {
            int lin = tid + it * 256;            // 0..1023
            int r = lin >> 3, c4 = lin & 7;
            float4 v = yq[lin];
            ys[(c4 * 4 + 0) * QP2 + r] = v.x;
            ys[(c4 * 4 + 1) * QP2 + r] = v.y;
            ys[(c4 * 4 + 2) * QP2 + r] = v.z;
            ys[(c4 * 4 + 3) * QP2 + r] = v.w;
        }
    }

    // ---- preload k-tile k0 into buffer 0 (natural + transposed) ----
    {
        const float4* xg = (const float4*)(xb + k0 * 64 * C_);
        float4 p0 = xg[tid], p1 = xg[tid + 256];
        int r = tid >> 3, c4 = tid & 7;
        *(float4*)&xN0[r * 36 + c4 * 4] = p0;
        xT0[(c4 * 4 + 0) * 68 + r] = p0.x;
        xT0[(c4 * 4 + 1) * 68 + r] = p0.y;
        xT0[(c4 * 4 + 2) * 68 + r] = p0.z;
        xT0[(c4 * 4 + 3) * 68 + r] = p0.w;
        int r2 = r + 32;
        *(float4*)&xN0[r2 * 36 + c4 * 4] = p1;
        xT0[(c4 * 4 + 0) * 68 + r2] = p1.x;
        xT0[(c4 * 4 + 1) * 68 + r2] = p1.y;
        xT0[(c4 * 4 + 2) * 68 + r2] = p1.z;
        xT0[(c4 * 4 + 3) * 68 + r2] = p1.w;
    }

    float l_i[8];
    #pragma unroll
    for (int i = 0; i < 8; i++) l_i[i] = 0.f;
    ull z2[4][2];
    #pragma unroll
    for (int i = 0; i < 4; i++) { z2[i][0] = 0ull; z2[i][1] = 0ull; }

    for (int kt = k0; kt < k1; kt++) {
        const int buf = (kt - k0) & 1;
        const float* xTb = xT0 + buf * XT_STR;
        const float* xNb = xN0 + buf * XN_STR;

        __syncthreads();   // (A) this buf loaded; prior Z-pass done; ys ready

        // prefetch next k-tile into registers (stored after S-pass)
        float4 p0, p1;
        const bool pf = (kt + 1 < k1);
        if (pf) {
            const float4* xg = (const float4*)(xb + (kt + 1) * 64 * C_);
            p0 = xg[tid]; p1 = xg[tid + 256];
        }

        // ---- S = y * x_k^T : 8q x 4k, q-paired FFMA2, pair-free q loads ----
        ull s2[4][4];   // [k-col j][q-pair i2]
        #pragma unroll
        for (int j = 0; j < 4; j++)
            #pragma unroll
            for (int i2 = 0; i2 < 4; i2++) s2[j][i2] = 0ull;

        #pragma unroll 8
        for (int c = 0; c < C_; c++) {
            ulonglong2 qa = *(const ulonglong2*)&ys[c * QP2 + ty * 8];
            ulonglong2 qb = *(const ulonglong2*)&ys[c * QP2 + ty * 8 + 4];
            float4 kv = *(const float4*)&xTb[c * 68 + tx * 4];
            ull kd[4] = { pack2(kv.x, kv.x), pack2(kv.y, kv.y),
                          pack2(kv.z, kv.z), pack2(kv.w, kv.w) };
            #pragma unroll
            for (int j = 0; j < 4; j++) {
                fma2(s2[j][0], qa.x, kd[j]);
                fma2(s2[j][1], qa.y, kd[j]);
                fma2(s2[j][2], qb.x, kd[j]);
                fma2(s2[j][3], qb.y, kd[j]);
            }
        }

        float s[8][4];
        #pragma unroll
        for (int j = 0; j < 4; j++)
            #pragma unroll
            for (int i2 = 0; i2 < 4; i2++) {
                float2 u = unpack2(s2[j][i2]);
                s[2 * i2 + 0][j] = u.x;
                s[2 * i2 + 1][j] = u.y;
            }

        if (kt >= 2 * qt) {   // causal mask (last two k-tiles of this qt)
            const int koff = (kt - 2 * qt) * 64;
            #pragma unroll
            for (int i = 0; i < 8; i++)
                #pragma unroll
                for (int j = 0; j < 4; j++)
                    if (koff + tx * 4 + j > ty * 8 + i) s[i][j] = -1e30f;
        }

        // ---- store prefetched tile into other buffer ----
        if (pf) {
            const int nb = buf ^ 1;
            float* xNn = xN0 + nb * XN_STR;
            float* xTn = xT0 + nb * XT_STR;
            int r = tid >> 3, c4 = tid & 7;
            *(float4*)&xNn[r * 36 + c4 * 4] = p0;
            xTn[(c4 * 4 + 0) * 68 + r] = p0.x;
            xTn[(c4 * 4 + 1) * 68 + r] = p0.y;
            xTn[(c4 * 4 + 2) * 68 + r] = p0.z;
            xTn[(c4 * 4 + 3) * 68 + r] = p0.w;
            int r2 = r + 32;
            *(float4*)&xNn[r2 * 36 + c4 * 4] = p1;
            xTn[(c4 * 4 + 0) * 68 + r2] = p1.x;
            xTn[(c4 * 4 + 1) * 68 + r2] = p1.y;
            xTn[(c4 * 4 + 2) * 68 + r2] = p1.z;
            xTn[(c4 * 4 + 3) * 68 + r2] = p1.w;
        }

        // ---- p = exp(s), accumulate local row-sum ----
        #pragma unroll
        for (int i = 0; i < 8; i++) {
            float e0 = __expf(s[i][0]);
            float e1 = __expf(s[i][1]);
            float e2 = __expf(s[i][2]);
            float e3 = __expf(s[i][3]);
            l_i[i] += (e0 + e1) + (e2 + e3);
            *(float4*)&Ps[(ty * 8 + i) * 68 + tx * 4] = make_float4(e0, e1, e2, e3);
        }
        __syncthreads();   // (B) Ps visible

        // ---- Z += P * x_k : rows zr+32i, cols zc..zc+3, c-paired FFMA2 ----
        #pragma unroll 4
        for (int k4 = 0; k4 < 16; k4++) {
            ulonglong2 xp[4];
            float4 pr[4];
            #pragma unroll
            for (int kk = 0; kk < 4; kk++)
                xp[kk] = *(const ulonglong2*)&xNb[(k4 * 4 + kk) * 36 + zc];
            #pragma unroll
            for (int i = 0; i < 4; i++)
                pr[i] = *(const float4*)&Ps[(zr + 32 * i) * 68 + k4 * 4];

            #pragma unroll
            for (int i = 0; i < 4; i++) {
                const float* pv = (const float*)&pr[i];
                #pragma unroll
                for (int kk = 0; kk < 4; kk++) {
                    ull pd = pack2(pv[kk], pv[kk]);
                    fma2(z2[i][0], pd, xp[kk].x);
                    fma2(z2[i][1], pd, xp[kk].y);
                }
            }
        }
    }

    // ---- write partials ----
    const int islot = (b * NQT128 + qt) * NCHUNK + chunk;

    #pragma unroll
    for (int i = 0; i < 8; i++) {   // partial row sums (reduced over tx)
        float rs = l_i[i];
        rs += __shfl_xor_sync(0xffffffffu, rs, 8);
        rs += __shfl_xor_sync(0xffffffffu, rs, 4);
        rs += __shfl_xor_sync(0xffffffffu, rs, 2);
        rs += __shfl_xor_sync(0xffffffffu, rs, 1);
        if (tx == 0) g_partL[islot * 128 + ty * 8 + i] = rs;
    }

    float* zp = g_partZ + islot * (128 * 32);
    #pragma unroll
    for (int i = 0; i < 4; i++) {
        float2 a = unpack2(z2[i][0]);
        float2 c = unpack2(z2[i][1]);
        *(float4*)&zp[(zr + 32 * i) * 32 + zc] = make_float4(a.x, a.y, c.x, c.y);
    }
}

// ---------------------------------------------------------------------------
// Kernel 2: reduce partials, out = (Z / l) * Wv.
// One CTA = (b, qt, half): 64 q-rows.  512 CTAs (proven config); nc <= 16.
// ---------------------------------------------------------------------------
__global__ __launch_bounds__(256) void reduce_kernel(
    const float* __restrict__ Wv, float* __restrict__ out)
{
    __shared__ float Zs[64][36];
    __shared__ float Wvs[32][68];
    __shared__ float lv[64];

    const int qt   = blockIdx.x >> 1;
    const int half = blockIdx.x & 1;
    const int b    = blockIdx.y;
    const int tid  = threadIdx.x;
    const int nc   = (2 * qt + 1) / CHUNKP + 1;   // valid chunks for this qt
    const int base = (b * NQT128 + qt) * NCHUNK;
    const int row0 = half * 64;

    float4 acc[2];
    #pragma unroll
    for (int it = 0; it < 2; it++) acc[it] = make_float4(0.f, 0.f, 0.f, 0.f);
    for (int s = 0; s < nc; s++) {
        const float4* zp = (const float4*)(g_partZ + (base + s) * (128 * 32) + row0 * 32);
        #pragma unroll
        for (int it = 0; it < 2; it++) {
            float4 v = zp[tid + it * 256];
            acc[it].x += v.x; acc[it].y += v.y; acc[it].z += v.z; acc[it].w += v.w;
        }
    }
    if (tid < 64) {
        float ls = 0.f;
        for (int s = 0; s < nc; s++)
            ls += g_partL[(base + s) * 128 + row0 + tid];
        lv[tid] = 1.f / ls;
    }
    __syncthreads();

    #pragma unroll
    for (int it = 0; it < 2; it++) {
        int lin = tid + it * 256;
        int r = lin >> 3, c4 = lin & 7;
        float li = lv[r];
        *(float4*)&Zs[r][c4 * 4] = make_float4(acc[it].x * li, acc[it].y * li,
                                               acc[it].z * li, acc[it].w * li);
    }
    {
        const float4* wg = (const float4*)Wv;
        #pragma unroll
        for (int it = 0; it < 2; it++) {
            int lin = tid + it * 256;
            int r = lin >> 4, c4 = lin & 15;
            *(float4*)&Wvs[r][c4 * 4] = wg[lin];
        }
    }
    __syncthreads();

    const int tx = tid & 15, ty = tid >> 4;
    float o[4][4];
    #pragma unroll
    for (int i = 0; i < 4; i++)
        #pragma unroll
        for (int j = 0; j < 4; j++) o[i][j] = 0.f;

    #pragma unroll 4
    for (int c = 0; c < C_; c++) {
        float4 w4 = *(const float4*)&Wvs[c][tx * 4];
        #pragma unroll
        for (int i = 0; i < 4; i++) {
            float zv = Zs[ty + 16 * i][c];
            o[i][0] += zv * w4.x; o[i][1] += zv * w4.y;
            o[i][2] += zv * w4.z; o[i][3] += zv * w4.w;
        }
    }

    float* Og = out + (b * T_ + qt * 128 + row0) * D_;
    #pragma unroll
    for (int i = 0; i < 4; i++)
        *(float4*)&Og[(ty + 16 * i) * D_ + tx * 4] =
            make_float4(o[i][0], o[i][1], o[i][2], o[i][3]);
}

// ---------------------------------------------------------------------------
extern "C" void kernel_launch(void* const* d_in, const int* in_sizes, int n_in,
                              void* d_out, int out_size)
{
    const float* x  = (const float*)d_in[0];
    const float* Wk = (const float*)d_in[1];
    const float* Wq = (const float*)d_in[2];
    const float* Wv = (const float*)d_in[3];
    float* out = (float*)d_out;

    y_kernel<<<(B_ * T_) / 128, 256>>>(x, Wk, Wq);

    const int smem = SM_FLOATS * (int)sizeof(float);   // 87552 B
    cudaFuncSetAttribute(attn_kernel, cudaFuncAttributeMaxDynamicSharedMemorySize, smem);
    attn_kernel<<<dim3(NQT128 * NCHUNK, B_), 256, smem>>>(x);

    reduce_kernel<<<dim3(NQT128 * 2, B_), 256>>>(Wv, out);
}